// round 10
// baseline (speedup 1.0000x reference)
#include <cuda_runtime.h>
#include <cuda_bf16.h>

// ---------------------------------------------------------------------------
// MultiLayerGnn: 3-layer GCN (+linear skips) + global_sort_pool top-K
// N=50000, E=800000, F_IN=H=64, C_OUT=32, K=1024
// Column-split layers: conv halves + skip GEMM on FMA stream, agg halves on
// LTS stream, event-pipelined. All FP math bit-identical to the r8 kernel.
// As pad = 68 floats (272B) to keep LDS.128 16B-aligned (r9 bug: pad 65).
// ---------------------------------------------------------------------------

#define NMAX 50000
#define EMAX 800000
#define KTOP 1024

static constexpr size_t AL(size_t x) { return (x + 255) & ~size_t(255); }

static constexpr size_t OFF_HWA  = 0;
static constexpr size_t OFF_HWB  = AL(OFF_HWA  + (size_t)NMAX * 32 * 4);
static constexpr size_t OFF_S    = AL(OFF_HWB  + (size_t)NMAX * 32 * 4);
static constexpr size_t OFF_H1   = AL(OFF_S    + (size_t)NMAX * 64 * 4);
static constexpr size_t OFF_H2   = AL(OFF_H1   + (size_t)NMAX * 64 * 4);
static constexpr size_t OFF_DINV = AL(OFF_H2   + (size_t)NMAX * 64 * 4);
static constexpr size_t OFF_DEG  = AL(OFF_DINV + (size_t)NMAX * 4);
static constexpr size_t OFF_FILL = AL(OFF_DEG  + (size_t)NMAX * 4);
static constexpr size_t OFF_RP   = AL(OFF_FILL + (size_t)NMAX * 4);
static constexpr size_t OFF_EDG  = AL(OFF_RP   + (size_t)(NMAX + 1) * 4);
static constexpr size_t OFF_SKEY = AL(OFF_EDG  + (size_t)EMAX * 8);
static constexpr size_t OFF_HIST = AL(OFF_SKEY + (size_t)NMAX * 4);
static constexpr size_t OFF_BSUM = AL(OFF_HIST + 4096 * 4);
static constexpr size_t SCRATCH_TOTAL = AL(OFF_BSUM + 256 * 4);

__device__ __align__(256) unsigned char g_scratch[SCRATCH_TOTAL];

// ---------------------------------------------------------------------------
// f32x2 packed-FMA helpers (bit-identical per-lane to fmaf)
// ---------------------------------------------------------------------------

#define FMA2(d, a, b, c) \
    asm("fma.rn.f32x2 %0, %1, %2, %3;" : "=l"(d) : "l"(a), "l"(b), "l"(c))

__device__ __forceinline__ unsigned long long dup2(float x) {
    unsigned long long r; unsigned u = __float_as_uint(x);
    asm("mov.b64 %0, {%1, %2};" : "=l"(r) : "r"(u), "r"(u));
    return r;
}

__device__ __forceinline__ float2 unpk2(unsigned long long v) {
    unsigned lo, hi;
    asm("mov.b64 {%0, %1}, %2;" : "=r"(lo), "=r"(hi) : "l"(v));
    return make_float2(__uint_as_float(lo), __uint_as_float(hi));
}

// ---------------------------------------------------------------------------
// Prep kernels (deg = edge-only count, self-loop via d+1; init via memset)
// ---------------------------------------------------------------------------

__global__ void deg_kernel(const int* __restrict__ ei, int e,
                           int* __restrict__ deg, int n) {
    int i = blockIdx.x * blockDim.x + threadIdx.x;
    if (i >= e) return;
    unsigned d = (unsigned)ei[e + i];
    if (d < (unsigned)n) atomicAdd(&deg[d], 1);
}

__global__ void scanA(const int* __restrict__ deg, float* __restrict__ dinv,
                      int* __restrict__ bsum, int n) {
    __shared__ int sh[256];
    int t = threadIdx.x;
    int i = blockIdx.x * 256 + t;
    int v = 0;
    if (i < n) {
        int d = deg[i];
        dinv[i] = rsqrtf((float)(d + 1));
        v = d;
    }
    sh[t] = v;
    __syncthreads();
    for (int off = 128; off > 0; off >>= 1) {
        if (t < off) sh[t] += sh[t + off];
        __syncthreads();
    }
    if (t == 0) bsum[blockIdx.x] = sh[0];
}

__global__ void scanC2(const int* __restrict__ deg, const int* __restrict__ bsum,
                       int* __restrict__ rowptr, int nb, int n) {
    __shared__ int sh[256];
    __shared__ int pref;
    int t = threadIdx.x, bid = blockIdx.x;
    sh[t] = (t < bid) ? bsum[t] : 0;     // nb <= 256
    __syncthreads();
    for (int off = 128; off > 0; off >>= 1) {
        if (t < off) sh[t] += sh[t + off];
        __syncthreads();
    }
    if (t == 0) pref = sh[0];
    __syncthreads();
    int i = bid * 256 + t;
    int v = (i < n) ? deg[i] : 0;
    sh[t] = v;
    __syncthreads();
    for (int off = 1; off < 256; off <<= 1) {
        int x = (t >= off) ? sh[t - off] : 0;
        __syncthreads();
        sh[t] += x;
        __syncthreads();
    }
    if (i < n) rowptr[i] = pref + sh[t] - v;
    if (bid == nb - 1 && t == 0) rowptr[n] = pref + bsum[bid];
}

// Builds merged {src, norm} 8B edge records.
__global__ void scatter_kernel(const int* __restrict__ ei, int e,
                               const float* __restrict__ dinv,
                               const int* __restrict__ rowptr,
                               int* __restrict__ fill,
                               int2* __restrict__ edges, int n) {
    int i = blockIdx.x * blockDim.x + threadIdx.x;
    if (i >= e) return;
    unsigned s = (unsigned)ei[i];
    unsigned d = (unsigned)ei[e + i];
    if (s >= (unsigned)n || d >= (unsigned)n) return;
    int p = atomicAdd(&fill[d], 1);
    edges[rowptr[d] + p] = make_int2((int)s, __float_as_int(dinv[s] * dinv[d]));
}

// ---------------------------------------------------------------------------
// GEMMs (f32x2). As transposed, pad 68 floats (16B-aligned rows, bank rotate).
// ---------------------------------------------------------------------------

#define APAD 68

// conv slice: out[N x 32] = h[N x 64] @ W[:, c0:c0+32]   (W row stride ws)
__global__ __launch_bounds__(128) void gemm_conv(
    const float* __restrict__ h, const float* __restrict__ W, int ws, int c0,
    float* __restrict__ out, int n) {
    __shared__ float As[64][APAD];
    __shared__ float Ws[64][32];

    int tid = threadIdx.x;
    int base = blockIdx.x * 64;

    for (int f = tid; f < 64 * 16; f += 128) {
        int row = f >> 4, c4 = f & 15;
        float4 v = make_float4(0.f, 0.f, 0.f, 0.f);
        int gr = base + row;
        if (gr < n) v = ((const float4*)h)[(size_t)gr * 16 + c4];
        int k = c4 * 4;
        As[k + 0][row] = v.x;
        As[k + 1][row] = v.y;
        As[k + 2][row] = v.z;
        As[k + 3][row] = v.w;
    }
    for (int f = tid; f < 64 * 32; f += 128) {
        int k = f >> 5, j = f & 31;
        Ws[k][j] = W[k * ws + c0 + j];
    }
    __syncthreads();

    int tcol = tid & 15, trow = tid >> 4;
    unsigned long long acc2[8];
#pragma unroll
    for (int i = 0; i < 8; i++) acc2[i] = 0ull;

#pragma unroll 4
    for (int k = 0; k < 64; k++) {
        float4 a0 = *(const float4*)&As[k][trow * 8];
        float4 a1 = *(const float4*)&As[k][trow * 8 + 4];
        float a[8] = {a0.x, a0.y, a0.z, a0.w, a1.x, a1.y, a1.z, a1.w};
        unsigned long long w2 = *(const unsigned long long*)&Ws[k][tcol * 2];
#pragma unroll
        for (int i = 0; i < 8; i++) {
            unsigned long long ad = dup2(a[i]);
            FMA2(acc2[i], ad, w2, acc2[i]);
        }
    }

#pragma unroll
    for (int i = 0; i < 8; i++) {
        int gr = base + trow * 8 + i;
        if (gr >= n) continue;
        float2 p = unpk2(acc2[i]);
        *(float2*)&out[(size_t)gr * 32 + tcol * 2] = p;
    }
}

// skip GEMM: S[N x 64] = b + 0.5*(h @ Wl + bl)
__global__ __launch_bounds__(128) void gemm_skip(
    const float* __restrict__ h, const float* __restrict__ Wl,
    const float* __restrict__ b, const float* __restrict__ bl,
    float* __restrict__ S, int n) {
    __shared__ float As[64][APAD];
    __shared__ float Ws[64][64];

    int tid = threadIdx.x;
    int base = blockIdx.x * 64;

    for (int f = tid; f < 64 * 16; f += 128) {
        int row = f >> 4, c4 = f & 15;
        float4 v = make_float4(0.f, 0.f, 0.f, 0.f);
        int gr = base + row;
        if (gr < n) v = ((const float4*)h)[(size_t)gr * 16 + c4];
        int k = c4 * 4;
        As[k + 0][row] = v.x;
        As[k + 1][row] = v.y;
        As[k + 2][row] = v.z;
        As[k + 3][row] = v.w;
    }
    for (int f = tid; f < 64 * 64; f += 128) {
        int k = f >> 6, j = f & 63;
        Ws[k][j] = Wl[k * 64 + j];
    }
    __syncthreads();

    int tcol = tid & 15, trow = tid >> 4;
    unsigned long long acc2[8][2];
#pragma unroll
    for (int i = 0; i < 8; i++) { acc2[i][0] = 0ull; acc2[i][1] = 0ull; }

#pragma unroll 4
    for (int k = 0; k < 64; k++) {
        float4 a0 = *(const float4*)&As[k][trow * 8];
        float4 a1 = *(const float4*)&As[k][trow * 8 + 4];
        float a[8] = {a0.x, a0.y, a0.z, a0.w, a1.x, a1.y, a1.z, a1.w};
        unsigned long long w0 = *(const unsigned long long*)&Ws[k][tcol * 4];
        unsigned long long w1 = *(const unsigned long long*)&Ws[k][tcol * 4 + 2];
#pragma unroll
        for (int i = 0; i < 8; i++) {
            unsigned long long ad = dup2(a[i]);
            FMA2(acc2[i][0], ad, w0, acc2[i][0]);
            FMA2(acc2[i][1], ad, w1, acc2[i][1]);
        }
    }

#pragma unroll
    for (int i = 0; i < 8; i++) {
        int gr = base + trow * 8 + i;
        if (gr >= n) continue;
#pragma unroll
        for (int c = 0; c < 2; c++) {
            int j = tcol * 4 + 2 * c;
            float2 p = unpk2(acc2[i][c]);
            float2 o;
            o.x = b[j]     + 0.5f * (p.x + bl[j]);
            o.y = b[j + 1] + 0.5f * (p.y + bl[j + 1]);
            *(float2*)&S[(size_t)gr * 64 + j] = o;
        }
    }
}

// ---------------------------------------------------------------------------
// Aggregation halves: warp/node, lane = channel (c0+lane).
// hout[.,c0+lane] = relu(S[.,c0+lane] + di2*hwH[node] + sum norm*hwH[src])
// ---------------------------------------------------------------------------

__global__ void agg_half(const float* __restrict__ hwH, const float* __restrict__ S,
                         int c0, const float* __restrict__ dinv,
                         const int* __restrict__ rowptr,
                         const int2* __restrict__ edges,
                         float* __restrict__ hout, int n) {
    int w = (blockIdx.x * blockDim.x + threadIdx.x) >> 5;
    int lane = threadIdx.x & 31;
    if (w >= n) return;
    float di = dinv[w];
    float acc = hwH[(size_t)w * 32 + lane] * (di * di);
    int e = rowptr[w], e1 = rowptr[w + 1];
    for (; e + 3 < e1; e += 4) {
        int2 d0 = edges[e],     d1 = edges[e + 1];
        int2 d2 = edges[e + 2], d3 = edges[e + 3];
        float v0 = hwH[(size_t)d0.x * 32 + lane];
        float v1 = hwH[(size_t)d1.x * 32 + lane];
        float v2 = hwH[(size_t)d2.x * 32 + lane];
        float v3 = hwH[(size_t)d3.x * 32 + lane];
        acc = fmaf(v0, __int_as_float(d0.y), acc);
        acc = fmaf(v1, __int_as_float(d1.y), acc);
        acc = fmaf(v2, __int_as_float(d2.y), acc);
        acc = fmaf(v3, __int_as_float(d3.y), acc);
    }
    for (; e < e1; e++) {
        int2 d0 = edges[e];
        acc = fmaf(hwH[(size_t)d0.x * 32 + lane], __int_as_float(d0.y), acc);
    }
    float v = S[(size_t)w * 64 + c0 + lane] + acc;
    hout[(size_t)w * 64 + c0 + lane] = fmaxf(v, 0.f);
}

// Layer-3 agg (32 ch) + fused sort-key + hist1 (lane 31 owns channel 31).
__global__ void agg32_key(const float* __restrict__ hw3, const float* __restrict__ bias,
                          const float* __restrict__ dinv,
                          const int* __restrict__ rowptr,
                          const int2* __restrict__ edges,
                          float* __restrict__ out, int n,
                          unsigned* __restrict__ skey, int* __restrict__ hist1) {
    int w = (blockIdx.x * blockDim.x + threadIdx.x) >> 5;
    int lane = threadIdx.x & 31;
    if (w >= n) return;
    float di = dinv[w];
    float acc = hw3[(size_t)w * 32 + lane] * (di * di);
    int e = rowptr[w], e1 = rowptr[w + 1];
    for (; e + 3 < e1; e += 4) {
        int2 d0 = edges[e],     d1 = edges[e + 1];
        int2 d2 = edges[e + 2], d3 = edges[e + 3];
        float v0 = hw3[(size_t)d0.x * 32 + lane];
        float v1 = hw3[(size_t)d1.x * 32 + lane];
        float v2 = hw3[(size_t)d2.x * 32 + lane];
        float v3 = hw3[(size_t)d3.x * 32 + lane];
        acc = fmaf(v0, __int_as_float(d0.y), acc);
        acc = fmaf(v1, __int_as_float(d1.y), acc);
        acc = fmaf(v2, __int_as_float(d2.y), acc);
        acc = fmaf(v3, __int_as_float(d3.y), acc);
    }
    for (; e < e1; e++) {
        int2 d0 = edges[e];
        acc = fmaf(hw3[(size_t)d0.x * 32 + lane], __int_as_float(d0.y), acc);
    }
    float v = acc + bias[lane];
    out[(size_t)w * 32 + lane] = v;
    if (lane == 31) {
        unsigned u = __float_as_uint(v);
        unsigned s = (u & 0x80000000u) ? ~u : (u | 0x80000000u);
        skey[w] = s;
        atomicAdd(&hist1[s >> 20], 1);
    }
}

// ---------------------------------------------------------------------------
// Merged top-K finisher (unchanged from r8)
// ---------------------------------------------------------------------------

__device__ __forceinline__ void findbin_warp(const int* __restrict__ hist,
                                             int base, int need,
                                             int* outB, int* outCum) {
    int lane = threadIdx.x & 31;
    int hi = 4095 - 128 * lane;
    int s = 0;
    for (int k = 0; k < 128; k++) s += hist[hi - k];
    int incl = s;
#pragma unroll
    for (int off = 1; off < 32; off <<= 1) {
        int x = __shfl_up_sync(0xFFFFFFFFu, incl, off);
        if (lane >= off) incl += x;
    }
    int excl = incl - s;
    if (base + excl < need && base + incl >= need) {
        int c = base + excl;
        int b = hi;
        while (c + hist[b] < need) { c += hist[b]; b--; }
        *outB = b;
        *outCum = c;
    }
}

__global__ __launch_bounds__(1024) void select_topk(
    const unsigned* __restrict__ skey, int n,
    const int* __restrict__ hist1,
    const float* __restrict__ h3, float* __restrict__ out) {
    __shared__ unsigned long long sd[4096];
    __shared__ int B1, C1, B2, C2, scnt;
    __shared__ unsigned Tsh;
    int* hist2 = (int*)sd;
    int tid = threadIdx.x;

    if (tid == 0) scnt = 0;
    for (int i = tid; i < 4096; i += 1024) hist2[i] = 0;
    __syncthreads();

    if (tid < 32) findbin_warp(hist1, 0, KTOP, &B1, &C1);
    __syncthreads();
    int b1 = B1, c1 = C1;

    for (int i = tid; i < n; i += 1024) {
        unsigned s = skey[i];
        if ((int)(s >> 20) == b1) atomicAdd(&hist2[(s >> 8) & 0xFFF], 1);
    }
    __syncthreads();

    if (tid < 32) findbin_warp(hist2, c1, KTOP, &B2, &C2);
    __syncthreads();
    if (tid == 0) Tsh = (((unsigned)b1) << 20) | (((unsigned)B2) << 8);
    __syncthreads();
    unsigned T = Tsh;
    __syncthreads();

    for (int i = tid; i < n; i += 1024) {
        unsigned s = skey[i];
        if (s >= T) {
            int p = atomicAdd(&scnt, 1);
            if (p < 4096)
                sd[p] = (((unsigned long long)s) << 32) |
                        (unsigned long long)(0xFFFFFFFFu - (unsigned)i);
        }
    }
    __syncthreads();

    int C = scnt; if (C > 4096) C = 4096;
    int S = 1024; while (S < C) S <<= 1;
    for (int i = tid; i < S; i += 1024) if (i >= C) sd[i] = 0ull;
    __syncthreads();
    for (int k = 2; k <= S; k <<= 1) {
        for (int j = k >> 1; j > 0; j >>= 1) {
            for (int t = tid; t < S; t += 1024) {
                int ixj = t ^ j;
                if (ixj > t) {
                    bool up = ((t & k) == 0);
                    unsigned long long A = sd[t], Bv = sd[ixj];
                    bool sw = up ? (A < Bv) : (A > Bv);
                    if (sw) { sd[t] = Bv; sd[ixj] = A; }
                }
            }
            __syncthreads();
        }
    }
    for (int t = tid; t < KTOP * 32; t += 1024) {
        int r = t >> 5, c = t & 31;
        unsigned idx = 0xFFFFFFFFu - (unsigned)(sd[r] & 0xFFFFFFFFull);
        out[t] = h3[(size_t)idx * 32 + c];
    }
}

// ---------------------------------------------------------------------------
// Launch: FMA work on main, prep+agg (LTS) on s2, event-pipelined.
// ---------------------------------------------------------------------------

extern "C" void kernel_launch(void* const* d_in, const int* in_sizes, int n_in,
                              void* d_out, int out_size) {
    const float* x   = (const float*)d_in[0];
    const float* W1  = (const float*)d_in[1];
    const float* b1  = (const float*)d_in[2];
    const float* Wl1 = (const float*)d_in[3];
    const float* bl1 = (const float*)d_in[4];
    const float* W2  = (const float*)d_in[5];
    const float* b2  = (const float*)d_in[6];
    const float* Wl2 = (const float*)d_in[7];
    const float* bl2 = (const float*)d_in[8];
    const float* W3  = (const float*)d_in[9];
    const float* b3  = (const float*)d_in[10];
    const int*   ei  = (const int*)d_in[11];

    int n = in_sizes[0] / 64;
    int e = in_sizes[11] / 2;

    unsigned char* base = nullptr;
    cudaGetSymbolAddress((void**)&base, g_scratch);

    float* hwA     = (float*)(base + OFF_HWA);
    float* hwB     = (float*)(base + OFF_HWB);
    float* Sbuf    = (float*)(base + OFF_S);
    float* h1      = (float*)(base + OFF_H1);
    float* h2      = (float*)(base + OFF_H2);
    float* dinv    = (float*)(base + OFF_DINV);
    int*   deg     = (int*)(base + OFF_DEG);
    int*   fill    = (int*)(base + OFF_FILL);
    int*   rowptr  = (int*)(base + OFF_RP);
    int2*  edges   = (int2*)(base + OFF_EDG);
    unsigned* skey = (unsigned*)(base + OFF_SKEY);
    int*   hist1   = (int*)(base + OFF_HIST);
    int*   bsum    = (int*)(base + OFF_BSUM);
    float* h3      = Sbuf;   // reuse S region after layer-2 aggs finish

    int nb = (n + 255) / 256;
    int gblocks = (n + 63) / 64;
    int ablocks = (n + 7) / 8;

    cudaStream_t s2;
    cudaStreamCreate(&s2);
    cudaEvent_t evFork, evS1, evB1, evG1, evS2, evB2, evG2;
    cudaEventCreateWithFlags(&evFork, cudaEventDisableTiming);
    cudaEventCreateWithFlags(&evS1, cudaEventDisableTiming);
    cudaEventCreateWithFlags(&evB1, cudaEventDisableTiming);
    cudaEventCreateWithFlags(&evG1, cudaEventDisableTiming);
    cudaEventCreateWithFlags(&evS2, cudaEventDisableTiming);
    cudaEventCreateWithFlags(&evB2, cudaEventDisableTiming);
    cudaEventCreateWithFlags(&evG2, cudaEventDisableTiming);

    cudaEventRecord(evFork, 0);
    cudaStreamWaitEvent(s2, evFork, 0);

    // ---- prep branch (s2) ----
    cudaMemsetAsync(deg, 0, (size_t)n * 4, s2);
    cudaMemsetAsync(fill, 0, (size_t)n * 4, s2);
    cudaMemsetAsync(hist1, 0, 4096 * 4, s2);
    deg_kernel<<<(e + 255) / 256, 256, 0, s2>>>(ei, e, deg, n);
    scanA<<<nb, 256, 0, s2>>>(deg, dinv, bsum, n);
    scanC2<<<nb, 256, 0, s2>>>(deg, bsum, rowptr, nb, n);
    scatter_kernel<<<(e + 255) / 256, 256, 0, s2>>>(ei, e, dinv, rowptr, fill, edges, n);

    // ---- layer 1 GEMMs (main; independent of CSR) ----
    gemm_conv<<<gblocks, 128>>>(x, W1, 64, 0, hwA, n);
    gemm_skip<<<gblocks, 128>>>(x, Wl1, b1, bl1, Sbuf, n);
    cudaEventRecord(evS1, 0);                    // convA1 + skip1 done
    gemm_conv<<<gblocks, 128>>>(x, W1, 64, 32, hwB, n);
    cudaEventRecord(evB1, 0);                    // convB1 done

    // ---- layer 1 aggs (s2, after CSR + GEMMs) ----
    cudaStreamWaitEvent(s2, evS1, 0);
    agg_half<<<ablocks, 256, 0, s2>>>(hwA, Sbuf, 0, dinv, rowptr, edges, h1, n);
    cudaStreamWaitEvent(s2, evB1, 0);
    agg_half<<<ablocks, 256, 0, s2>>>(hwB, Sbuf, 32, dinv, rowptr, edges, h1, n);
    cudaEventRecord(evG1, s2);

    // ---- layer 2 GEMMs (main, after h1) ----
    cudaStreamWaitEvent(0, evG1, 0);
    gemm_conv<<<gblocks, 128>>>(h1, W2, 64, 0, hwA, n);
    gemm_skip<<<gblocks, 128>>>(h1, Wl2, b2, bl2, Sbuf, n);
    cudaEventRecord(evS2, 0);
    gemm_conv<<<gblocks, 128>>>(h1, W2, 64, 32, hwB, n);
    cudaEventRecord(evB2, 0);

    // ---- layer 2 aggs (s2) ----
    cudaStreamWaitEvent(s2, evS2, 0);
    agg_half<<<ablocks, 256, 0, s2>>>(hwA, Sbuf, 0, dinv, rowptr, edges, h2, n);
    cudaStreamWaitEvent(s2, evB2, 0);
    agg_half<<<ablocks, 256, 0, s2>>>(hwB, Sbuf, 32, dinv, rowptr, edges, h2, n);
    cudaEventRecord(evG2, s2);

    // ---- layer 3 + top-K (main) ----
    cudaStreamWaitEvent(0, evG2, 0);
    gemm_conv<<<gblocks, 128>>>(h2, W3, 32, 0, hwA, n);
    agg32_key<<<ablocks, 256>>>(hwA, b3, dinv, rowptr, edges, h3, n, skey, hist1);
    select_topk<<<1, 1024>>>(skey, n, hist1, h3, (float*)d_out);

    cudaEventDestroy(evFork);
    cudaEventDestroy(evS1);
    cudaEventDestroy(evB1);
    cudaEventDestroy(evG1);
    cudaEventDestroy(evS2);
    cudaEventDestroy(evB2);
    cudaEventDestroy(evG2);
    cudaStreamDestroy(s2);
}

// round 11
// speedup vs baseline: 1.1954x; 1.1954x over previous
#include <cuda_runtime.h>
#include <cuda_bf16.h>

// ---------------------------------------------------------------------------
// MultiLayerGnn: 3-layer GCN (+linear skips) + global_sort_pool top-K
// N=50000, E=800000, F_IN=H=64, C_OUT=32, K=1024
// r8 architecture (fused skip GEMM + full-width agg) + int2 merged edges.
// ---------------------------------------------------------------------------

#define NMAX 50000
#define EMAX 800000
#define KTOP 1024

static constexpr size_t AL(size_t x) { return (x + 255) & ~size_t(255); }

static constexpr size_t OFF_HW   = 0;
static constexpr size_t OFF_ACCA = AL(OFF_HW   + (size_t)NMAX * 64 * 4);
static constexpr size_t OFF_ACCB = AL(OFF_ACCA + (size_t)NMAX * 64 * 4);
static constexpr size_t OFF_DINV = AL(OFF_ACCB + (size_t)NMAX * 64 * 4);
static constexpr size_t OFF_DEG  = AL(OFF_DINV + (size_t)NMAX * 4);
static constexpr size_t OFF_FILL = AL(OFF_DEG  + (size_t)NMAX * 4);
static constexpr size_t OFF_RP   = AL(OFF_FILL + (size_t)NMAX * 4);
static constexpr size_t OFF_EDG  = AL(OFF_RP   + (size_t)(NMAX + 1) * 4);
static constexpr size_t OFF_SKEY = AL(OFF_EDG  + (size_t)EMAX * 8);
static constexpr size_t OFF_H1   = AL(OFF_SKEY + (size_t)NMAX * 4);
static constexpr size_t OFF_BSUM = AL(OFF_H1   + 4096 * 4);
static constexpr size_t SCRATCH_TOTAL = AL(OFF_BSUM + 256 * 4);

__device__ __align__(256) unsigned char g_scratch[SCRATCH_TOTAL];

// ---------------------------------------------------------------------------
// f32x2 packed-FMA helpers (bit-identical per-lane to fmaf)
// ---------------------------------------------------------------------------

#define FMA2(d, a, b, c) \
    asm("fma.rn.f32x2 %0, %1, %2, %3;" : "=l"(d) : "l"(a), "l"(b), "l"(c))

__device__ __forceinline__ unsigned long long dup2(float x) {
    unsigned long long r; unsigned u = __float_as_uint(x);
    asm("mov.b64 %0, {%1, %2};" : "=l"(r) : "r"(u), "r"(u));
    return r;
}

__device__ __forceinline__ float2 unpk2(unsigned long long v) {
    unsigned lo, hi;
    asm("mov.b64 {%0, %1}, %2;" : "=r"(lo), "=r"(hi) : "l"(v));
    return make_float2(__uint_as_float(lo), __uint_as_float(hi));
}

// ---------------------------------------------------------------------------
// Prep kernels (deg = edge-only count; self-loop via d+1; init via memset)
// ---------------------------------------------------------------------------

__global__ void deg_kernel(const int* __restrict__ ei, int e,
                           int* __restrict__ deg, int n) {
    int i = blockIdx.x * blockDim.x + threadIdx.x;
    if (i >= e) return;
    unsigned d = (unsigned)ei[e + i];
    if (d < (unsigned)n) atomicAdd(&deg[d], 1);
}

// Phase A: per-block sums of deg + fused dinv (= rsqrt(deg+1))
__global__ void scanA(const int* __restrict__ deg, float* __restrict__ dinv,
                      int* __restrict__ bsum, int n) {
    __shared__ int sh[256];
    int t = threadIdx.x;
    int i = blockIdx.x * 256 + t;
    int v = 0;
    if (i < n) {
        int d = deg[i];
        dinv[i] = rsqrtf((float)(d + 1));
        v = d;
    }
    sh[t] = v;
    __syncthreads();
    for (int off = 128; off > 0; off >>= 1) {
        if (t < off) sh[t] += sh[t + off];
        __syncthreads();
    }
    if (t == 0) bsum[blockIdx.x] = sh[0];
}

// Phase C (fused B): each block computes its own prefix from bsum, then local scan.
__global__ void scanC2(const int* __restrict__ deg, const int* __restrict__ bsum,
                       int* __restrict__ rowptr, int nb, int n) {
    __shared__ int sh[256];
    __shared__ int pref;
    int t = threadIdx.x, bid = blockIdx.x;
    sh[t] = (t < bid) ? bsum[t] : 0;     // nb <= 256
    __syncthreads();
    for (int off = 128; off > 0; off >>= 1) {
        if (t < off) sh[t] += sh[t + off];
        __syncthreads();
    }
    if (t == 0) pref = sh[0];
    __syncthreads();
    int i = bid * 256 + t;
    int v = (i < n) ? deg[i] : 0;
    sh[t] = v;
    __syncthreads();
    for (int off = 1; off < 256; off <<= 1) {
        int x = (t >= off) ? sh[t - off] : 0;
        __syncthreads();
        sh[t] += x;
        __syncthreads();
    }
    if (i < n) rowptr[i] = pref + sh[t] - v;
    if (bid == nb - 1 && t == 0) rowptr[n] = pref + bsum[bid];
}

// Builds merged {src, norm} 8B edge records.
__global__ void scatter_kernel(const int* __restrict__ ei, int e,
                               const float* __restrict__ dinv,
                               const int* __restrict__ rowptr,
                               int* __restrict__ fill,
                               int2* __restrict__ edges, int n) {
    int i = blockIdx.x * blockDim.x + threadIdx.x;
    if (i >= e) return;
    unsigned s = (unsigned)ei[i];
    unsigned d = (unsigned)ei[e + i];
    if (s >= (unsigned)n || d >= (unsigned)n) return;
    int p = atomicAdd(&fill[d], 1);
    edges[rowptr[d] + p] = make_int2((int)s, __float_as_int(dinv[s] * dinv[d]));
}

// ---------------------------------------------------------------------------
// Fused GEMM via packed f32x2 FMA: hw = h @ W ; (skip) accout = b + 0.5*(h@Wl+bl)
// (byte-identical math to the proven r8 kernel)
// ---------------------------------------------------------------------------

template <int CW, bool SKIP>
__global__ __launch_bounds__(128) void gemm_fused(
    const float* __restrict__ hin,
    const float* __restrict__ W, const float* __restrict__ Wl,
    const float* __restrict__ b, const float* __restrict__ bl,
    float* __restrict__ hw, float* __restrict__ accout, int n) {
    constexpr int HOUT = SKIP ? CW / 2 : CW;
    constexpr int CT = CW / 16;
    constexpr int CT2 = CT / 2;
    __shared__ float As[64][64];   // As[k][row] (transposed)
    __shared__ float Ws[64][CW];

    int tid = threadIdx.x;
    int base = blockIdx.x * 64;

    for (int f = tid; f < 64 * 16; f += 128) {
        int row = f >> 4, c4 = f & 15;
        float4 v = make_float4(0.f, 0.f, 0.f, 0.f);
        int gr = base + row;
        if (gr < n) v = ((const float4*)hin)[(size_t)gr * 16 + c4];
        int k = c4 * 4;
        As[k + 0][row] = v.x;
        As[k + 1][row] = v.y;
        As[k + 2][row] = v.z;
        As[k + 3][row] = v.w;
    }
    for (int f = tid; f < 64 * CW; f += 128) {
        int k = f / CW, j = f % CW;
        float w;
        if (SKIP) w = (j < HOUT) ? W[k * HOUT + j] : Wl[k * HOUT + (j - HOUT)];
        else      w = W[k * CW + j];
        Ws[k][j] = w;
    }
    __syncthreads();

    int tcol = tid & 15, trow = tid >> 4;
    unsigned long long acc2[8][CT2];
#pragma unroll
    for (int i = 0; i < 8; i++)
#pragma unroll
        for (int c = 0; c < CT2; c++) acc2[i][c] = 0ull;

#pragma unroll 4
    for (int k = 0; k < 64; k++) {
        float4 a0 = *(const float4*)&As[k][trow * 8];
        float4 a1 = *(const float4*)&As[k][trow * 8 + 4];
        float a[8] = {a0.x, a0.y, a0.z, a0.w, a1.x, a1.y, a1.z, a1.w};
        unsigned long long w2[CT2];
#pragma unroll
        for (int c = 0; c < CT2; c++)
            w2[c] = *(const unsigned long long*)&Ws[k][tcol * CT + 2 * c];
#pragma unroll
        for (int i = 0; i < 8; i++) {
            unsigned long long ad = dup2(a[i]);
#pragma unroll
            for (int c = 0; c < CT2; c++)
                FMA2(acc2[i][c], ad, w2[c], acc2[i][c]);
        }
    }

#pragma unroll
    for (int i = 0; i < 8; i++) {
        int gr = base + trow * 8 + i;
        if (gr >= n) continue;
#pragma unroll
        for (int c = 0; c < CT2; c++) {
            int col = tcol * CT + 2 * c;
            float2 p = unpk2(acc2[i][c]);
            if (SKIP) {
                if (col < HOUT) {       // pair never straddles HOUT (col even, HOUT=64)
                    *(float2*)&hw[(size_t)gr * HOUT + col] = p;
                } else {
                    int j = col - HOUT;
                    accout[(size_t)gr * HOUT + j]     = b[j]     + 0.5f * (p.x + bl[j]);
                    accout[(size_t)gr * HOUT + j + 1] = b[j + 1] + 0.5f * (p.y + bl[j + 1]);
                }
            } else {
                *(float2*)&hw[(size_t)gr * CW + col] = p;
            }
        }
    }
}

// ---------------------------------------------------------------------------
// Aggregation: warp per node, CSR gather over merged int2 edges.
// ---------------------------------------------------------------------------

__global__ void agg64(const float* __restrict__ hw, const float* accin,
                      const float* __restrict__ dinv,
                      const int* __restrict__ rowptr,
                      const int2* __restrict__ edges,
                      float* out, int n) {
    int w = (blockIdx.x * blockDim.x + threadIdx.x) >> 5;
    int lane = threadIdx.x & 31;
    if (w >= n) return;
    const float2* hp = (const float2*)hw;
    float di = dinv[w];
    float di2 = di * di;
    float2 s2 = hp[(size_t)w * 32 + lane];
    float ax = s2.x * di2, ay = s2.y * di2;
    int e = rowptr[w], e1 = rowptr[w + 1];
    for (; e + 3 < e1; e += 4) {
        int2 d0 = edges[e],     d1 = edges[e + 1];
        int2 d2 = edges[e + 2], d3 = edges[e + 3];
        float2 v0 = hp[(size_t)d0.x * 32 + lane];
        float2 v1 = hp[(size_t)d1.x * 32 + lane];
        float2 v2 = hp[(size_t)d2.x * 32 + lane];
        float2 v3 = hp[(size_t)d3.x * 32 + lane];
        float n0 = __int_as_float(d0.y), n1 = __int_as_float(d1.y);
        float n2 = __int_as_float(d2.y), n3 = __int_as_float(d3.y);
        ax = fmaf(v0.x, n0, ax); ay = fmaf(v0.y, n0, ay);
        ax = fmaf(v1.x, n1, ax); ay = fmaf(v1.y, n1, ay);
        ax = fmaf(v2.x, n2, ax); ay = fmaf(v2.y, n2, ay);
        ax = fmaf(v3.x, n3, ax); ay = fmaf(v3.y, n3, ay);
    }
    for (; e < e1; e++) {
        int2 d0 = edges[e];
        float2 va = hp[(size_t)d0.x * 32 + lane];
        float na = __int_as_float(d0.y);
        ax = fmaf(va.x, na, ax); ay = fmaf(va.y, na, ay);
    }
    float2 bse = ((const float2*)accin)[(size_t)w * 32 + lane];
    float rx = fmaxf(bse.x + ax, 0.f);
    float ry = fmaxf(bse.y + ay, 0.f);
    ((float2*)out)[(size_t)w * 32 + lane] = make_float2(rx, ry);
}

// Layer-3 agg (32 ch) with fused sort-key + hist1 build (lane 31 owns ch 31).
__global__ void agg32_key(const float* __restrict__ hw, const float* __restrict__ bias,
                          const float* __restrict__ dinv,
                          const int* __restrict__ rowptr,
                          const int2* __restrict__ edges,
                          float* __restrict__ out, int n,
                          unsigned* __restrict__ skey, int* __restrict__ hist1) {
    int w = (blockIdx.x * blockDim.x + threadIdx.x) >> 5;
    int lane = threadIdx.x & 31;
    if (w >= n) return;
    float di = dinv[w];
    float di2 = di * di;
    float acc = hw[(size_t)w * 32 + lane] * di2;
    int e = rowptr[w], e1 = rowptr[w + 1];
    for (; e + 3 < e1; e += 4) {
        int2 d0 = edges[e],     d1 = edges[e + 1];
        int2 d2 = edges[e + 2], d3 = edges[e + 3];
        float v0 = hw[(size_t)d0.x * 32 + lane];
        float v1 = hw[(size_t)d1.x * 32 + lane];
        float v2 = hw[(size_t)d2.x * 32 + lane];
        float v3 = hw[(size_t)d3.x * 32 + lane];
        acc = fmaf(v0, __int_as_float(d0.y), acc);
        acc = fmaf(v1, __int_as_float(d1.y), acc);
        acc = fmaf(v2, __int_as_float(d2.y), acc);
        acc = fmaf(v3, __int_as_float(d3.y), acc);
    }
    for (; e < e1; e++) {
        int2 d0 = edges[e];
        acc = fmaf(hw[(size_t)d0.x * 32 + lane], __int_as_float(d0.y), acc);
    }
    float v = acc + bias[lane];
    out[(size_t)w * 32 + lane] = v;
    if (lane == 31) {
        unsigned u = __float_as_uint(v);
        unsigned s = (u & 0x80000000u) ? ~u : (u | 0x80000000u);
        skey[w] = s;
        atomicAdd(&hist1[s >> 20], 1);
    }
}

// ---------------------------------------------------------------------------
// Merged top-K finisher (unchanged from r8)
// ---------------------------------------------------------------------------

__device__ __forceinline__ void findbin_warp(const int* __restrict__ hist,
                                             int base, int need,
                                             int* outB, int* outCum) {
    int lane = threadIdx.x & 31;
    int hi = 4095 - 128 * lane;
    int s = 0;
    for (int k = 0; k < 128; k++) s += hist[hi - k];
    int incl = s;
#pragma unroll
    for (int off = 1; off < 32; off <<= 1) {
        int x = __shfl_up_sync(0xFFFFFFFFu, incl, off);
        if (lane >= off) incl += x;
    }
    int excl = incl - s;
    if (base + excl < need && base + incl >= need) {
        int c = base + excl;
        int b = hi;
        while (c + hist[b] < need) { c += hist[b]; b--; }
        *outB = b;
        *outCum = c;
    }
}

__global__ __launch_bounds__(1024) void select_topk(
    const unsigned* __restrict__ skey, int n,
    const int* __restrict__ hist1,
    const float* __restrict__ h3, float* __restrict__ out) {
    __shared__ unsigned long long sd[4096];
    __shared__ int B1, C1, B2, C2, scnt;
    __shared__ unsigned Tsh;
    int* hist2 = (int*)sd;
    int tid = threadIdx.x;

    if (tid == 0) scnt = 0;
    for (int i = tid; i < 4096; i += 1024) hist2[i] = 0;
    __syncthreads();

    if (tid < 32) findbin_warp(hist1, 0, KTOP, &B1, &C1);
    __syncthreads();
    int b1 = B1, c1 = C1;

    for (int i = tid; i < n; i += 1024) {
        unsigned s = skey[i];
        if ((int)(s >> 20) == b1) atomicAdd(&hist2[(s >> 8) & 0xFFF], 1);
    }
    __syncthreads();

    if (tid < 32) findbin_warp(hist2, c1, KTOP, &B2, &C2);
    __syncthreads();
    if (tid == 0) Tsh = (((unsigned)b1) << 20) | (((unsigned)B2) << 8);
    __syncthreads();
    unsigned T = Tsh;
    __syncthreads();

    for (int i = tid; i < n; i += 1024) {
        unsigned s = skey[i];
        if (s >= T) {
            int p = atomicAdd(&scnt, 1);
            if (p < 4096)
                sd[p] = (((unsigned long long)s) << 32) |
                        (unsigned long long)(0xFFFFFFFFu - (unsigned)i);
        }
    }
    __syncthreads();

    int C = scnt; if (C > 4096) C = 4096;
    int S = 1024; while (S < C) S <<= 1;
    for (int i = tid; i < S; i += 1024) if (i >= C) sd[i] = 0ull;
    __syncthreads();
    for (int k = 2; k <= S; k <<= 1) {
        for (int j = k >> 1; j > 0; j >>= 1) {
            for (int t = tid; t < S; t += 1024) {
                int ixj = t ^ j;
                if (ixj > t) {
                    bool up = ((t & k) == 0);
                    unsigned long long A = sd[t], Bv = sd[ixj];
                    bool sw = up ? (A < Bv) : (A > Bv);
                    if (sw) { sd[t] = Bv; sd[ixj] = A; }
                }
            }
            __syncthreads();
        }
    }
    for (int t = tid; t < KTOP * 32; t += 1024) {
        int r = t >> 5, c = t & 31;
        unsigned idx = 0xFFFFFFFFu - (unsigned)(sd[r] & 0xFFFFFFFFull);
        out[t] = h3[(size_t)idx * 32 + c];
    }
}

// ---------------------------------------------------------------------------
// Launch (prep branch overlapped with GEMM layer 1 via stream fork/join)
// ---------------------------------------------------------------------------

extern "C" void kernel_launch(void* const* d_in, const int* in_sizes, int n_in,
                              void* d_out, int out_size) {
    const float* x   = (const float*)d_in[0];
    const float* W1  = (const float*)d_in[1];
    const float* b1  = (const float*)d_in[2];
    const float* Wl1 = (const float*)d_in[3];
    const float* bl1 = (const float*)d_in[4];
    const float* W2  = (const float*)d_in[5];
    const float* b2  = (const float*)d_in[6];
    const float* Wl2 = (const float*)d_in[7];
    const float* bl2 = (const float*)d_in[8];
    const float* W3  = (const float*)d_in[9];
    const float* b3  = (const float*)d_in[10];
    const int*   ei  = (const int*)d_in[11];   // int32 per harness dtype map

    int n = in_sizes[0] / 64;
    int e = in_sizes[11] / 2;

    unsigned char* base = nullptr;
    cudaGetSymbolAddress((void**)&base, g_scratch);

    float* hw      = (float*)(base + OFF_HW);
    float* accA    = (float*)(base + OFF_ACCA);
    float* accB    = (float*)(base + OFF_ACCB);
    float* dinv    = (float*)(base + OFF_DINV);
    int*   deg     = (int*)(base + OFF_DEG);
    int*   fill    = (int*)(base + OFF_FILL);
    int*   rowptr  = (int*)(base + OFF_RP);
    int2*  edges   = (int2*)(base + OFF_EDG);
    unsigned* skey = (unsigned*)(base + OFF_SKEY);
    int*   hist1   = (int*)(base + OFF_H1);
    int*   bsum    = (int*)(base + OFF_BSUM);

    int nb = (n + 255) / 256;
    int gblocks = (n + 63) / 64;
    int ablocks = (n + 7) / 8;

    cudaStream_t s2;
    cudaStreamCreate(&s2);
    cudaEvent_t evFork, evJoin;
    cudaEventCreateWithFlags(&evFork, cudaEventDisableTiming);
    cudaEventCreateWithFlags(&evJoin, cudaEventDisableTiming);

    cudaEventRecord(evFork, 0);
    cudaStreamWaitEvent(s2, evFork, 0);

    // prep branch (s2)
    cudaMemsetAsync(deg, 0, (size_t)n * 4, s2);
    cudaMemsetAsync(fill, 0, (size_t)n * 4, s2);
    cudaMemsetAsync(hist1, 0, 4096 * 4, s2);
    deg_kernel<<<(e + 255) / 256, 256, 0, s2>>>(ei, e, deg, n);
    scanA<<<nb, 256, 0, s2>>>(deg, dinv, bsum, n);
    scanC2<<<nb, 256, 0, s2>>>(deg, bsum, rowptr, nb, n);
    scatter_kernel<<<(e + 255) / 256, 256, 0, s2>>>(ei, e, dinv, rowptr, fill, edges, n);
    cudaEventRecord(evJoin, s2);

    // main stream: GEMM layer 1 (independent of CSR)
    gemm_fused<128, true><<<gblocks, 128>>>(x, W1, Wl1, b1, bl1, hw, accA, n);

    // join
    cudaStreamWaitEvent(0, evJoin, 0);

    agg64<<<ablocks, 256>>>(hw, accA, dinv, rowptr, edges, accA, n);
    // Layer 2
    gemm_fused<128, true><<<gblocks, 128>>>(accA, W2, Wl2, b2, bl2, hw, accB, n);
    agg64<<<ablocks, 256>>>(hw, accB, dinv, rowptr, edges, accB, n);
    // Layer 3 (no skip, 32 channels) + fused key/hist
    gemm_fused<32, false><<<gblocks, 128>>>(accB, W3, nullptr, nullptr, nullptr, hw, nullptr, n);
    agg32_key<<<ablocks, 256>>>(hw, b3, dinv, rowptr, edges, accA, n, skey, hist1);

    // Merged top-K finisher
    select_topk<<<1, 1024>>>(skey, n, hist1, accA, (float*)d_out);

    cudaEventDestroy(evFork);
    cudaEventDestroy(evJoin);
    cudaStreamDestroy(s2);
}